// round 8
// baseline (speedup 1.0000x reference)
#include <cuda_runtime.h>

// Shapes (fixed by the problem)
#define BB   4
#define CC   128
#define HH   64
#define WW   64
#define HWSZ 4096              // 64*64
#define CHW  (CC*HWSZ)         // 128*4096

// Scratch (device globals -- no allocation allowed)
__device__ float g_buf[BB*CHW];   // silu(GN(x)) / silu(GN(h))
__device__ float g_h[BB*CHW];     // h
__device__ float g_c[BB*CHW];     // c = 1x1 conv of cond
__device__ float g_temb[BB*CC];   // time embedding

__device__ __forceinline__ float silu_f(float v) { return v / (1.0f + __expf(-v)); }

// ---- packed fp32x2 helpers (sm_103a FFMA2 path) ----
__device__ __forceinline__ unsigned long long pack2(float lo, float hi) {
    unsigned long long r;
    asm("mov.b64 %0,{%1,%2};" : "=l"(r) : "f"(lo), "f"(hi));
    return r;
}
__device__ __forceinline__ float2 unpack2(unsigned long long v) {
    float2 f;
    asm("mov.b64 {%0,%1},%2;" : "=f"(f.x), "=f"(f.y) : "l"(v));
    return f;
}
__device__ __forceinline__ void fma2(unsigned long long& d,
                                     unsigned long long a,
                                     unsigned long long b) {
    asm("fma.rn.f32x2 %0,%1,%2,%0;" : "+l"(d) : "l"(a), "l"(b));
}

// ---------------------------------------------------------------------------
// temb[b,o] = sum_k silu(t[b,k]) * mlp_w[o,k] + mlp_b[o]     (tiny)
// ---------------------------------------------------------------------------
__global__ void temb_kernel(const float* __restrict__ t,
                            const float* __restrict__ w,
                            const float* __restrict__ bias) {
    __shared__ float st[BB*512];
    int tid = threadIdx.x;
    for (int e = tid; e < BB*512; e += 512) st[e] = silu_f(t[e]);
    __syncthreads();
    int b = tid >> 7, o = tid & 127;
    const float* wr = w + o*512;
    const float* tr = st + b*512;
    float s = 0.f;
#pragma unroll 8
    for (int k = 0; k < 512; ++k) s += tr[k]*wr[k];
    g_temb[tid] = s + bias[o];
}

// ---------------------------------------------------------------------------
// GroupNorm(32 groups) + SiLU.  One block per (b,g). grid 128, block 256.
// ---------------------------------------------------------------------------
__global__ void gn_silu_kernel(const float* __restrict__ in,
                               const float* __restrict__ scale,
                               const float* __restrict__ bias,
                               float* __restrict__ out) {
    __shared__ float red[32];
    int tid = threadIdx.x;
    const float4* p = (const float4*)(in  + (size_t)blockIdx.x * 16384);
    float4*       q = (float4*)      (out + (size_t)blockIdx.x * 16384);
    float s = 0.f, sq = 0.f;
#pragma unroll 4
    for (int k = 0; k < 16; ++k) {
        float4 a = p[tid + k*256];
        s  += a.x + a.y + a.z + a.w;
        sq += a.x*a.x + a.y*a.y + a.z*a.z + a.w*a.w;
    }
#pragma unroll
    for (int o = 16; o > 0; o >>= 1) {
        s  += __shfl_xor_sync(0xffffffffu, s,  o);
        sq += __shfl_xor_sync(0xffffffffu, sq, o);
    }
    int wp = tid >> 5, lane = tid & 31;
    if (lane == 0) { red[wp] = s; red[wp + 8] = sq; }
    __syncthreads();
    if (tid == 0) {
        float ts = 0.f, tq2 = 0.f;
        for (int i = 0; i < 8; ++i) { ts += red[i]; tq2 += red[i + 8]; }
        float mean = ts * (1.0f/16384.0f);
        float var  = tq2 * (1.0f/16384.0f) - mean*mean;
        red[16] = mean;
        red[17] = rsqrtf(var + 1e-5f);
    }
    __syncthreads();
    float mean = red[16], rstd = red[17];
    int g = blockIdx.x & 31;
#pragma unroll 4
    for (int k = 0; k < 16; ++k) {
        int idx = tid + k*256;
        int c = g*4 + (idx >> 10);
        float sc = scale[c] * rstd;
        float bi = bias[c] - mean * sc;
        float4 a = p[idx];
        float4 r;
        r.x = silu_f(fmaf(a.x, sc, bi));
        r.y = silu_f(fmaf(a.y, sc, bi));
        r.z = silu_f(fmaf(a.z, sc, bi));
        r.w = silu_f(fmaf(a.w, sc, bi));
        q[idx] = r;
    }
}

// ---------------------------------------------------------------------------
// 3x3 conv, pad 1.  CTA: 16x16 pixel tile x 32 out channels, b fixed.
// grid (16 tiles, 4 o-blocks, 4 batch), block 256.
// Thread: 2x2 pixels x 8 out channels, FFMA2 inner (pairs over out channels).
// ---------------------------------------------------------------------------
__global__ void __launch_bounds__(256) conv3x3_kernel(
    const float* __restrict__ in, const float* __restrict__ wgt,
    const float* __restrict__ bias, const float* __restrict__ temb,
    const float* __restrict__ resid, float* __restrict__ out) {
    __shared__ float sIn[8*18*18];            // 2592 floats
    __shared__ float sW[72*34];               // [ci*9+rs][o], stride 34 (even!)
    int tid = threadIdx.x;
    int b  = blockIdx.z;
    int ob = blockIdx.y * 32;
    int tx0 = (blockIdx.x & 3) * 16;
    int ty0 = (blockIdx.x >> 2) * 16;
    int og = tid & 3;                         // out-channel group (8 each)
    int pb = tid >> 2;                        // 0..63 pixel blocks
    int lx = (pb & 7) * 2;
    int ly = (pb >> 3) * 2;
    // acc2[jp][p] = { acc[o=og*8+2jp][pix p], acc[o+1][pix p] }
    unsigned long long acc2[4][4];
#pragma unroll
    for (int j = 0; j < 4; ++j)
#pragma unroll
        for (int i = 0; i < 4; ++i) acc2[j][i] = 0ull;

    const float* inb = in + (size_t)b * CHW;
    const float* wb  = wgt + (size_t)ob * 1152;       // 128*9

    for (int cc = 0; cc < 16; ++cc) {
        __syncthreads();
        int ci0 = cc * 8;
        for (int e = tid; e < 2592; e += 256) {
            int ci = e / 324; int rem = e - ci*324;
            int yy = rem / 18; int xx = rem - yy*18;
            int gy = ty0 - 1 + yy, gx = tx0 - 1 + xx;
            float v = 0.f;
            if ((unsigned)gy < 64u && (unsigned)gx < 64u)
                v = inb[(ci0 + ci)*HWSZ + gy*64 + gx];
            sIn[e] = v;
        }
        for (int e = tid; e < 2304; e += 256) {
            int o = e / 72; int irs = e - o*72;       // irs = ci*9 + rs
            sW[irs*34 + o] = wb[o*1152 + ci0*9 + irs];
        }
        __syncthreads();
#pragma unroll 2
        for (int ci = 0; ci < 8; ++ci) {
            const float* sbase = sIn + ci*324;
#pragma unroll
            for (int rs = 0; rs < 9; ++rs) {
                int r = rs / 3, sx = rs - (rs/3)*3;
                const float* rowp = sbase + (ly + r)*18 + lx + sx;
                float x00 = rowp[0],  x01 = rowp[1];
                float x10 = rowp[18], x11 = rowp[19];
                unsigned long long xb0 = pack2(x00, x00);
                unsigned long long xb1 = pack2(x01, x01);
                unsigned long long xb2 = pack2(x10, x10);
                unsigned long long xb3 = pack2(x11, x11);
                const unsigned long long* wq =
                    (const unsigned long long*)(sW + (ci*9 + rs)*34 + og*8);
#pragma unroll
                for (int jp = 0; jp < 4; ++jp) {
                    unsigned long long wv = wq[jp];
                    fma2(acc2[jp][0], xb0, wv);
                    fma2(acc2[jp][1], xb1, wv);
                    fma2(acc2[jp][2], xb2, wv);
                    fma2(acc2[jp][3], xb3, wv);
                }
            }
        }
    }
    int px = tx0 + lx, py = ty0 + ly;
#pragma unroll
    for (int jp = 0; jp < 4; ++jp) {
        float2 v0 = unpack2(acc2[jp][0]);
        float2 v1 = unpack2(acc2[jp][1]);
        float2 v2 = unpack2(acc2[jp][2]);
        float2 v3 = unpack2(acc2[jp][3]);
        float pe[2][4] = {{v0.x, v1.x, v2.x, v3.x}, {v0.y, v1.y, v2.y, v3.y}};
#pragma unroll
        for (int oo = 0; oo < 2; ++oo) {
            int o = ob + og*8 + 2*jp + oo;
            float add = bias[o];
            if (temb) add += temb[b*CC + o];
            int base = (b*CC + o) * HWSZ;
#pragma unroll
            for (int dy = 0; dy < 2; ++dy)
#pragma unroll
                for (int dx = 0; dx < 2; ++dx) {
                    int idx = base + (py + dy)*64 + (px + dx);
                    float v = pe[oo][dy*2 + dx] + add;
                    if (resid) v += resid[idx];
                    out[idx] = v;
                }
        }
    }
}

// ---------------------------------------------------------------------------
// 1x1 conv -> g_c.  grid (32 o-groups, 4 px-chunks, 4 batch), block 256.
// Thread: 4 outs x 4 px (one float4 column).  512 CTAs for occupancy.
// ---------------------------------------------------------------------------
__global__ void __launch_bounds__(256) cond1x1_kernel(
    const float* __restrict__ cond, const float* __restrict__ w,
    const float* __restrict__ bias) {
    __shared__ float sw[512];
    int tid = threadIdx.x;
    int o0 = blockIdx.x * 4;
    int ch = blockIdx.y;                // 1024-px chunk
    int b  = blockIdx.z;
    for (int e = tid; e < 512; e += 256)
        sw[e] = w[(o0 + (e >> 7))*128 + (e & 127)];
    __syncthreads();
    float4 acc[4];
#pragma unroll
    for (int j = 0; j < 4; ++j) acc[j] = make_float4(0.f, 0.f, 0.f, 0.f);
    const float4* cp = (const float4*)(cond + (size_t)b * CHW) + ch*256 + tid;
#pragma unroll 4
    for (int i = 0; i < 128; ++i) {
        float4 xv = cp[(size_t)i * 1024];
#pragma unroll
        for (int j = 0; j < 4; ++j) {
            float wv = sw[j*128 + i];
            acc[j].x = fmaf(wv, xv.x, acc[j].x);
            acc[j].y = fmaf(wv, xv.y, acc[j].y);
            acc[j].z = fmaf(wv, xv.z, acc[j].z);
            acc[j].w = fmaf(wv, xv.w, acc[j].w);
        }
    }
#pragma unroll
    for (int j = 0; j < 4; ++j) {
        float bj = bias[o0 + j];
        float4 v = acc[j];
        v.x += bj; v.y += bj; v.z += bj; v.w += bj;
        ((float4*)(g_c + ((size_t)b*CC + o0 + j) * HWSZ))[ch*256 + tid] = v;
    }
}

// ---------------------------------------------------------------------------
// Streaming spatial cross-attention + contrast-embed add.  FFMA2 version.
// One CTA per (b, w-PAIR): s = wo*64 + hh  (wo in {0,1}), 128 q per chunk.
// A[qq][s] = sum_c H[c][s]*C[c][qq] (128x128), softmax over hh within
// (qq,wo), Out[c][s] += C * P^T.  Thread tiles are 8x8 (FFMA2 pairs along s).
// grid (32 w-pairs, 4 b), block 256, dynamic smem 192KB (1 CTA/SM).
// ---------------------------------------------------------------------------
__global__ void __launch_bounds__(256) attn_kernel(
    float* __restrict__ h, const float* __restrict__ cmat,
    const float* __restrict__ ce_tab, const int* __restrict__ aim) {
    extern __shared__ float smem[];
    float* sH = smem;               // [128 c][128 s]
    float* sC = smem + 16384;       // [128 c][128 qq]
    float* sA = smem + 32768;       // [128 qq][128 s]
    int tid = threadIdx.x;
    int w0 = blockIdx.x * 2;
    int b  = blockIdx.y;
    float*       hb = h    + (size_t)b * CHW;
    const float* cb = cmat + (size_t)b * CHW;

    // load H for both w columns
    for (int e = tid; e < 16384; e += 256) {
        int c = e >> 7, s = e & 127;
        int wo = s >> 6, hh = s & 63;
        sH[e] = hb[c*HWSZ + hh*64 + w0 + wo];
    }

    const int ts = tid & 15;        // s blocking: s in {ts*4..+3} U {64+ts*4..+3}
    const int tg = tid >> 4;        // q-group (A-gemm) / c-group (Out-gemm), x8
    const int lane = tid & 31, wp = tid >> 5;
    const float SCALE = 0.08838834764831845f;   // 1/sqrt(128)

    // Out accumulators: oa[j][p] = {Out[c][s0], Out[c][s0+1]}
    unsigned long long oa[8][4];
#pragma unroll
    for (int j = 0; j < 8; ++j)
#pragma unroll
        for (int p = 0; p < 4; ++p) oa[j][p] = 0ull;

    for (int qc = 0; qc < 32; ++qc) {
        __syncthreads();            // previous iter done with sC/sA
        {   // load sC coalesced (128 q contiguous per channel)
            const float4* src = (const float4*)(cb + qc*128);
            float4* dst = (float4*)sC;
            for (int e = tid; e < 4096; e += 256) {
                int c = e >> 5, q4 = e & 31;
                dst[e] = src[(size_t)c*1024 + q4];
            }
        }
        __syncthreads();
        // --- A-gemm: qq = tg*8+j, s pairs at ts*4 (+64) ---
        unsigned long long a2[8][4];
#pragma unroll
        for (int j = 0; j < 8; ++j)
#pragma unroll
            for (int p = 0; p < 4; ++p) a2[j][p] = 0ull;
#pragma unroll 2
        for (int c = 0; c < 128; ++c) {
            ulonglong2 h0 = *(const ulonglong2*)(sH + c*128 + ts*4);
            ulonglong2 h1 = *(const ulonglong2*)(sH + c*128 + 64 + ts*4);
            float4 c0 = *(const float4*)(sC + c*128 + tg*8);
            float4 c1 = *(const float4*)(sC + c*128 + tg*8 + 4);
            unsigned long long hp0 = h0.x, hp1 = h0.y, hp2 = h1.x, hp3 = h1.y;
            unsigned long long cbk[8] = {
                pack2(c0.x, c0.x), pack2(c0.y, c0.y),
                pack2(c0.z, c0.z), pack2(c0.w, c0.w),
                pack2(c1.x, c1.x), pack2(c1.y, c1.y),
                pack2(c1.z, c1.z), pack2(c1.w, c1.w)};
#pragma unroll
            for (int j = 0; j < 8; ++j) {
                fma2(a2[j][0], cbk[j], hp0);
                fma2(a2[j][1], cbk[j], hp1);
                fma2(a2[j][2], cbk[j], hp2);
                fma2(a2[j][3], cbk[j], hp3);
            }
        }
        // store A tile (conflict-free: 16B stride over lanes)
#pragma unroll
        for (int j = 0; j < 8; ++j) {
            int row = (tg*8 + j) * 128;
            ulonglong2 v0; v0.x = a2[j][0]; v0.y = a2[j][1];
            ulonglong2 v1; v1.x = a2[j][2]; v1.y = a2[j][3];
            *(ulonglong2*)(sA + row + ts*4)      = v0;
            *(ulonglong2*)(sA + row + 64 + ts*4) = v1;
        }
        __syncthreads();
        // --- softmax over hh within each (qq, wo): 256 groups of 64 ---
#pragma unroll
        for (int k = 0; k < 32; ++k) {
            int g = wp*32 + k;
            float* base = sA + (g >> 1)*128 + (g & 1)*64;
            float x0 = base[lane]*SCALE, x1 = base[lane + 32]*SCALE;
            float m = fmaxf(x0, x1);
#pragma unroll
            for (int o = 16; o > 0; o >>= 1)
                m = fmaxf(m, __shfl_xor_sync(0xffffffffu, m, o));
            float e0 = __expf(x0 - m), e1 = __expf(x1 - m);
            float ss = e0 + e1;
#pragma unroll
            for (int o = 16; o > 0; o >>= 1)
                ss += __shfl_xor_sync(0xffffffffu, ss, o);
            float inv = 1.0f / ss;
            base[lane]      = e0 * inv;
            base[lane + 32] = e1 * inv;
        }
        __syncthreads();
        // --- Out-gemm: c = tg*8+j, s pairs at ts*4 (+64) ---
#pragma unroll 2
        for (int qq = 0; qq < 128; ++qq) {
            ulonglong2 p0 = *(const ulonglong2*)(sA + qq*128 + ts*4);
            ulonglong2 p1 = *(const ulonglong2*)(sA + qq*128 + 64 + ts*4);
            unsigned long long pp0 = p0.x, pp1 = p0.y, pp2 = p1.x, pp3 = p1.y;
#pragma unroll
            for (int j = 0; j < 8; ++j) {
                float cv = sC[(tg*8 + j)*128 + qq];
                unsigned long long cb2 = pack2(cv, cv);
                fma2(oa[j][0], cb2, pp0);
                fma2(oa[j][1], cb2, pp1);
                fma2(oa[j][2], cb2, pp2);
                fma2(oa[j][3], cb2, pp3);
            }
        }
    }
    // --- epilogue: h += attn + contrast_embed[aim[b]] ---
    const float* ce = ce_tab + aim[b]*CC;
#pragma unroll
    for (int j = 0; j < 8; ++j) {
        int c = tg*8 + j;
        float cev = ce[c];
#pragma unroll
        for (int p = 0; p < 4; ++p) {
            float2 v = unpack2(oa[j][p]);
            int wo  = p >> 1;
            int hh0 = ts*4 + (p & 1)*2;
            float* hp = hb + c*HWSZ + hh0*64 + w0 + wo;
            hp[0]  += v.x + cev;
            hp[64] += v.y + cev;
        }
    }
}

// ---------------------------------------------------------------------------
extern "C" void kernel_launch(void* const* d_in, const int* in_sizes, int n_in,
                              void* d_out, int out_size) {
    (void)in_sizes; (void)n_in; (void)out_size;
    const float* x       = (const float*)d_in[0];
    const float* t       = (const float*)d_in[1];
    const int*   aim     = (const int*)  d_in[2];
    const float* cond    = (const float*)d_in[3];
    const float* gn1_s   = (const float*)d_in[4];
    const float* gn1_b   = (const float*)d_in[5];
    const float* conv1_w = (const float*)d_in[6];
    const float* conv1_b = (const float*)d_in[7];
    const float* mlp_w   = (const float*)d_in[8];
    const float* mlp_b   = (const float*)d_in[9];
    const float* cond_w  = (const float*)d_in[10];
    const float* cond_b  = (const float*)d_in[11];
    const float* gn2_s   = (const float*)d_in[12];
    const float* gn2_b   = (const float*)d_in[13];
    const float* conv2_w = (const float*)d_in[14];
    const float* conv2_b = (const float*)d_in[15];
    const float* ce      = (const float*)d_in[16];
    float* out = (float*)d_out;

    float *p_buf, *p_h, *p_c, *p_temb;
    cudaGetSymbolAddress((void**)&p_buf,  g_buf);
    cudaGetSymbolAddress((void**)&p_h,    g_h);
    cudaGetSymbolAddress((void**)&p_c,    g_c);
    cudaGetSymbolAddress((void**)&p_temb, g_temb);

    // temb = silu(t) @ mlp_w^T + mlp_b
    temb_kernel<<<1, 512>>>(t, mlp_w, mlp_b);
    // g_buf = silu(GN1(x))
    gn_silu_kernel<<<128, 256>>>(x, gn1_s, gn1_b, p_buf);
    // g_h = conv1(g_buf) + conv1_b + temb
    conv3x3_kernel<<<dim3(16, 4, 4), 256>>>(p_buf, conv1_w, conv1_b, p_temb,
                                            nullptr, p_h);
    // g_c = 1x1 conv of cond
    cond1x1_kernel<<<dim3(32, 4, 4), 256>>>(cond, cond_w, cond_b);
    // attention (in-place on g_h) + contrast embed
    cudaFuncSetAttribute(attn_kernel,
                         cudaFuncAttributeMaxDynamicSharedMemorySize, 196608);
    attn_kernel<<<dim3(32, 4), 256, 196608>>>(p_h, p_c, ce, aim);
    // g_buf = silu(GN2(g_h))
    gn_silu_kernel<<<128, 256>>>(p_h, gn2_s, gn2_b, p_buf);
    // out = conv2(g_buf) + conv2_b + x
    conv3x3_kernel<<<dim3(16, 4, 4), 256>>>(p_buf, conv2_w, conv2_b, nullptr,
                                            x, out);
}

// round 11
// speedup vs baseline: 1.4643x; 1.4643x over previous
#include <cuda_runtime.h>

// Shapes (fixed by the problem)
#define BB   4
#define CC   128
#define HH   64
#define WW   64
#define HWSZ 4096              // 64*64
#define CHW  (CC*HWSZ)         // 128*4096

// Scratch (device globals -- no allocation allowed)
__device__ float g_buf[BB*CHW];   // silu(GN(x)) / silu(GN(h))
__device__ float g_h[BB*CHW];     // h
__device__ float g_c[BB*CHW];     // c = 1x1 conv of cond
__device__ float g_temb[BB*CC];   // time embedding

__device__ __forceinline__ float silu_f(float v) { return v / (1.0f + __expf(-v)); }

// ---- packed fp32x2 helpers (sm_103a FFMA2 path) ----
__device__ __forceinline__ unsigned long long pack2(float lo, float hi) {
    unsigned long long r;
    asm("mov.b64 %0,{%1,%2};" : "=l"(r) : "f"(lo), "f"(hi));
    return r;
}
__device__ __forceinline__ float2 unpack2(unsigned long long v) {
    float2 f;
    asm("mov.b64 {%0,%1},%2;" : "=f"(f.x), "=f"(f.y) : "l"(v));
    return f;
}
__device__ __forceinline__ void fma2(unsigned long long& d,
                                     unsigned long long a,
                                     unsigned long long b) {
    asm("fma.rn.f32x2 %0,%1,%2,%0;" : "+l"(d) : "l"(a), "l"(b));
}

// ---------------------------------------------------------------------------
// temb[b,o] = sum_k silu(t[b,k]) * mlp_w[o,k] + mlp_b[o]     (tiny)
// ---------------------------------------------------------------------------
__global__ void temb_kernel(const float* __restrict__ t,
                            const float* __restrict__ w,
                            const float* __restrict__ bias) {
    __shared__ float st[BB*512];
    int tid = threadIdx.x;
    for (int e = tid; e < BB*512; e += 512) st[e] = silu_f(t[e]);
    __syncthreads();
    int b = tid >> 7, o = tid & 127;
    const float* wr = w + o*512;
    const float* tr = st + b*512;
    float s = 0.f;
#pragma unroll 8
    for (int k = 0; k < 512; ++k) s += tr[k]*wr[k];
    g_temb[tid] = s + bias[o];
}

// ---------------------------------------------------------------------------
// GroupNorm(32 groups) + SiLU.  One block per (b,g). grid 128, block 256.
// ---------------------------------------------------------------------------
__global__ void gn_silu_kernel(const float* __restrict__ in,
                               const float* __restrict__ scale,
                               const float* __restrict__ bias,
                               float* __restrict__ out) {
    __shared__ float red[32];
    int tid = threadIdx.x;
    const float4* p = (const float4*)(in  + (size_t)blockIdx.x * 16384);
    float4*       q = (float4*)      (out + (size_t)blockIdx.x * 16384);
    float s = 0.f, sq = 0.f;
#pragma unroll 4
    for (int k = 0; k < 16; ++k) {
        float4 a = p[tid + k*256];
        s  += a.x + a.y + a.z + a.w;
        sq += a.x*a.x + a.y*a.y + a.z*a.z + a.w*a.w;
    }
#pragma unroll
    for (int o = 16; o > 0; o >>= 1) {
        s  += __shfl_xor_sync(0xffffffffu, s,  o);
        sq += __shfl_xor_sync(0xffffffffu, sq, o);
    }
    int wp = tid >> 5, lane = tid & 31;
    if (lane == 0) { red[wp] = s; red[wp + 8] = sq; }
    __syncthreads();
    if (tid == 0) {
        float ts = 0.f, tq2 = 0.f;
        for (int i = 0; i < 8; ++i) { ts += red[i]; tq2 += red[i + 8]; }
        float mean = ts * (1.0f/16384.0f);
        float var  = tq2 * (1.0f/16384.0f) - mean*mean;
        red[16] = mean;
        red[17] = rsqrtf(var + 1e-5f);
    }
    __syncthreads();
    float mean = red[16], rstd = red[17];
    int g = blockIdx.x & 31;
#pragma unroll 4
    for (int k = 0; k < 16; ++k) {
        int idx = tid + k*256;
        int c = g*4 + (idx >> 10);
        float sc = scale[c] * rstd;
        float bi = bias[c] - mean * sc;
        float4 a = p[idx];
        float4 r;
        r.x = silu_f(fmaf(a.x, sc, bi));
        r.y = silu_f(fmaf(a.y, sc, bi));
        r.z = silu_f(fmaf(a.z, sc, bi));
        r.w = silu_f(fmaf(a.w, sc, bi));
        q[idx] = r;
    }
}

// ---------------------------------------------------------------------------
// 3x3 conv, pad 1.  CTA: 16x16 pixel tile x 32 out channels, b fixed.
// grid (16 tiles, 4 o-blocks, 4 batch), block 256.  (R6 known-good version)
// ---------------------------------------------------------------------------
__global__ void __launch_bounds__(256) conv3x3_kernel(
    const float* __restrict__ in, const float* __restrict__ wgt,
    const float* __restrict__ bias, const float* __restrict__ temb,
    const float* __restrict__ resid, float* __restrict__ out) {
    __shared__ float sIn[8*18*18];            // 2592 floats
    __shared__ float sW[72*33];               // [ci*9+rs][o], stride 33 (pad)
    int tid = threadIdx.x;
    int b  = blockIdx.z;
    int ob = blockIdx.y * 32;
    int tx0 = (blockIdx.x & 3) * 16;
    int ty0 = (blockIdx.x >> 2) * 16;
    int og = tid & 3;                         // out-channel group (8 each)
    int pb = tid >> 2;                        // 0..63 pixel blocks
    int lx = (pb & 7) * 2;
    int ly = (pb >> 3) * 2;
    float acc[8][4];
#pragma unroll
    for (int j = 0; j < 8; ++j)
#pragma unroll
        for (int i = 0; i < 4; ++i) acc[j][i] = 0.f;

    const float* inb = in + (size_t)b * CHW;
    const float* wb  = wgt + (size_t)ob * 1152;       // 128*9

    for (int cc = 0; cc < 16; ++cc) {
        __syncthreads();
        int ci0 = cc * 8;
        for (int e = tid; e < 2592; e += 256) {
            int ci = e / 324; int rem = e - ci*324;
            int yy = rem / 18; int xx = rem - yy*18;
            int gy = ty0 - 1 + yy, gx = tx0 - 1 + xx;
            float v = 0.f;
            if ((unsigned)gy < 64u && (unsigned)gx < 64u)
                v = inb[(ci0 + ci)*HWSZ + gy*64 + gx];
            sIn[e] = v;
        }
        for (int e = tid; e < 2304; e += 256) {
            int o = e / 72; int irs = e - o*72;       // irs = ci*9 + rs
            sW[irs*33 + o] = wb[o*1152 + ci0*9 + irs];
        }
        __syncthreads();
#pragma unroll 2
        for (int ci = 0; ci < 8; ++ci) {
            const float* sbase = sIn + ci*324;
#pragma unroll
            for (int rs = 0; rs < 9; ++rs) {
                int r = rs / 3, sx = rs - (rs/3)*3;
                const float* rowp = sbase + (ly + r)*18 + lx + sx;
                float x00 = rowp[0],  x01 = rowp[1];
                float x10 = rowp[18], x11 = rowp[19];
                const float* wp = sW + (ci*9 + rs)*33 + og*8;
#pragma unroll
                for (int j = 0; j < 8; ++j) {
                    float wv = wp[j];
                    acc[j][0] = fmaf(wv, x00, acc[j][0]);
                    acc[j][1] = fmaf(wv, x01, acc[j][1]);
                    acc[j][2] = fmaf(wv, x10, acc[j][2]);
                    acc[j][3] = fmaf(wv, x11, acc[j][3]);
                }
            }
        }
    }
    int px = tx0 + lx, py = ty0 + ly;
#pragma unroll
    for (int j = 0; j < 8; ++j) {
        int o = ob + og*8 + j;
        float add = bias[o];
        if (temb) add += temb[b*CC + o];
        int base = (b*CC + o) * HWSZ;
#pragma unroll
        for (int dy = 0; dy < 2; ++dy)
#pragma unroll
            for (int dx = 0; dx < 2; ++dx) {
                int idx = base + (py + dy)*64 + (px + dx);
                float v = acc[j][dy*2 + dx] + add;
                if (resid) v += resid[idx];
                out[idx] = v;
            }
    }
}

// ---------------------------------------------------------------------------
// 1x1 conv -> g_c.  grid (32 o-groups, 4 px-chunks, 4 batch), block 256.
// (R8 version: measured 31.6us)
// ---------------------------------------------------------------------------
__global__ void __launch_bounds__(256) cond1x1_kernel(
    const float* __restrict__ cond, const float* __restrict__ w,
    const float* __restrict__ bias) {
    __shared__ float sw[512];
    int tid = threadIdx.x;
    int o0 = blockIdx.x * 4;
    int ch = blockIdx.y;                // 1024-px chunk
    int b  = blockIdx.z;
    for (int e = tid; e < 512; e += 256)
        sw[e] = w[(o0 + (e >> 7))*128 + (e & 127)];
    __syncthreads();
    float4 acc[4];
#pragma unroll
    for (int j = 0; j < 4; ++j) acc[j] = make_float4(0.f, 0.f, 0.f, 0.f);
    const float4* cp = (const float4*)(cond + (size_t)b * CHW) + ch*256 + tid;
#pragma unroll 4
    for (int i = 0; i < 128; ++i) {
        float4 xv = cp[(size_t)i * 1024];
#pragma unroll
        for (int j = 0; j < 4; ++j) {
            float wv = sw[j*128 + i];
            acc[j].x = fmaf(wv, xv.x, acc[j].x);
            acc[j].y = fmaf(wv, xv.y, acc[j].y);
            acc[j].z = fmaf(wv, xv.z, acc[j].z);
            acc[j].w = fmaf(wv, xv.w, acc[j].w);
        }
    }
#pragma unroll
    for (int j = 0; j < 4; ++j) {
        float bj = bias[o0 + j];
        float4 v = acc[j];
        v.x += bj; v.y += bj; v.z += bj; v.w += bj;
        ((float4*)(g_c + ((size_t)b*CC + o0 + j) * HWSZ))[ch*256 + tid] = v;
    }
}

// ---------------------------------------------------------------------------
// Streaming spatial cross-attention + contrast-embed add.
// R6 structure (one CTA per (b,w), 64-q chunks, 80KB smem, 2 CTAs/SM) with
// FFMA2 on both gemms at UNCHANGED register count: pairs run along hh, which
// is contiguous in both thread tiles, so hv/pv float4 loads reinterpret as
// packed pairs for free; only the broadcast operand is duplicate-packed.
// grid (64 w, 4 b), block 256, dynamic smem 80KB.
// ---------------------------------------------------------------------------
__global__ void __launch_bounds__(256) attn_kernel(
    float* __restrict__ h, const float* __restrict__ cmat,
    const float* __restrict__ ce_tab, const int* __restrict__ aim) {
    extern __shared__ float smem[];
    float* sH = smem;             // [128 c][64 hh]
    float* sC = smem + 8192;      // [128 c][64 qq]
    float* sA = smem + 16384;     // [64 qq][64 hh]
    int tid = threadIdx.x;
    int w = blockIdx.x;
    int b = blockIdx.y;
    float*       hb = h    + (size_t)b * CHW;
    const float* cb = cmat + (size_t)b * CHW;

    for (int e = tid; e < 8192; e += 256) {
        int c = e >> 6, hh = e & 63;
        sH[e] = hb[c*HWSZ + hh*64 + w];
    }
    // Out accumulators: oa2[j][p] = {Out[c][hh0], Out[c][hh0+1]}, hh0=th*4+2p
    unsigned long long oa2[8][2];
#pragma unroll
    for (int j = 0; j < 8; ++j) { oa2[j][0] = 0ull; oa2[j][1] = 0ull; }

    const int th = tid & 15;          // -> hh base th*4
    const int tq = tid >> 4;          // -> q base tq*4 (A) / c base tq*8 (Out)
    const int lane = tid & 31, wp = tid >> 5;
    const float SCALE = 0.08838834764831845f;   // 1/sqrt(128)

    for (int qc = 0; qc < 64; ++qc) {
        __syncthreads();
        const float* csrc = cb + qc*64;
        for (int e = tid; e < 8192; e += 256) {
            int c = e >> 6, qq = e & 63;
            sC[e] = csrc[c*HWSZ + qq];
        }
        __syncthreads();
        // --- A = Hw^T * Cchunk ---  (4 q x 4 hh per thread, hh paired)
        unsigned long long a2[4][2];
#pragma unroll
        for (int i = 0; i < 4; ++i) { a2[i][0] = 0ull; a2[i][1] = 0ull; }
#pragma unroll 4
        for (int c = 0; c < 128; ++c) {
            ulonglong2 hv = *(const ulonglong2*)(sH + c*64 + th*4);
            float4 cv = *(const float4*)(sC + c*64 + tq*4);
            unsigned long long hp0 = hv.x, hp1 = hv.y;
            unsigned long long c0 = pack2(cv.x, cv.x);
            unsigned long long c1 = pack2(cv.y, cv.y);
            unsigned long long c2 = pack2(cv.z, cv.z);
            unsigned long long c3 = pack2(cv.w, cv.w);
            fma2(a2[0][0], c0, hp0); fma2(a2[0][1], c0, hp1);
            fma2(a2[1][0], c1, hp0); fma2(a2[1][1], c1, hp1);
            fma2(a2[2][0], c2, hp0); fma2(a2[2][1], c2, hp1);
            fma2(a2[3][0], c3, hp0); fma2(a2[3][1], c3, hp1);
        }
#pragma unroll
        for (int qi = 0; qi < 4; ++qi) {
            ulonglong2 v; v.x = a2[qi][0]; v.y = a2[qi][1];
            *(ulonglong2*)(sA + (tq*4 + qi)*64 + th*4) = v;
        }
        __syncthreads();
        // --- softmax along hh (each sA row, 64 entries); SCALE folded in ---
#pragma unroll
        for (int k = 0; k < 8; ++k) {
            int r = wp*8 + k;
            float x0 = sA[r*64 + lane]*SCALE, x1 = sA[r*64 + lane + 32]*SCALE;
            float m = fmaxf(x0, x1);
#pragma unroll
            for (int o = 16; o > 0; o >>= 1)
                m = fmaxf(m, __shfl_xor_sync(0xffffffffu, m, o));
            float e0 = __expf(x0 - m), e1 = __expf(x1 - m);
            float ss = e0 + e1;
#pragma unroll
            for (int o = 16; o > 0; o >>= 1)
                ss += __shfl_xor_sync(0xffffffffu, ss, o);
            float inv = 1.0f / ss;
            sA[r*64 + lane]      = e0 * inv;
            sA[r*64 + lane + 32] = e1 * inv;
        }
        __syncthreads();
        // --- Out += Cchunk * P^T ---  (8 c x 4 hh per thread, hh paired)
        const int cb8 = tq * 8;
#pragma unroll 2
        for (int qq = 0; qq < 64; ++qq) {
            ulonglong2 pv = *(const ulonglong2*)(sA + qq*64 + th*4);
            unsigned long long pp0 = pv.x, pp1 = pv.y;
#pragma unroll
            for (int j = 0; j < 8; ++j) {
                float cv = sC[(cb8 + j)*64 + qq];
                unsigned long long cb2 = pack2(cv, cv);
                fma2(oa2[j][0], cb2, pp0);
                fma2(oa2[j][1], cb2, pp1);
            }
        }
    }
    // --- epilogue: h += attn + contrast_embed[aim[b]] ---
    const float* ce = ce_tab + aim[b]*CC;
    const int cb8 = tq * 8;
#pragma unroll
    for (int j = 0; j < 8; ++j) {
        int c = cb8 + j;
        float cev = ce[c];
        float* hp = hb + c*HWSZ + w;
#pragma unroll
        for (int p = 0; p < 2; ++p) {
            float2 v = unpack2(oa2[j][p]);
            int hh0 = th*4 + 2*p;
            hp[hh0*64]       += v.x + cev;
            hp[(hh0 + 1)*64] += v.y + cev;
        }
    }
}

// ---------------------------------------------------------------------------
extern "C" void kernel_launch(void* const* d_in, const int* in_sizes, int n_in,
                              void* d_out, int out_size) {
    (void)in_sizes; (void)n_in; (void)out_size;
    const float* x       = (const float*)d_in[0];
    const float* t       = (const float*)d_in[1];
    const int*   aim     = (const int*)  d_in[2];
    const float* cond    = (const float*)d_in[3];
    const float* gn1_s   = (const float*)d_in[4];
    const float* gn1_b   = (const float*)d_in[5];
    const float* conv1_w = (const float*)d_in[6];
    const float* conv1_b = (const float*)d_in[7];
    const float* mlp_w   = (const float*)d_in[8];
    const float* mlp_b   = (const float*)d_in[9];
    const float* cond_w  = (const float*)d_in[10];
    const float* cond_b  = (const float*)d_in[11];
    const float* gn2_s   = (const float*)d_in[12];
    const float* gn2_b   = (const float*)d_in[13];
    const float* conv2_w = (const float*)d_in[14];
    const float* conv2_b = (const float*)d_in[15];
    const float* ce      = (const float*)d_in[16];
    float* out = (float*)d_out;

    float *p_buf, *p_h, *p_c, *p_temb;
    cudaGetSymbolAddress((void**)&p_buf,  g_buf);
    cudaGetSymbolAddress((void**)&p_h,    g_h);
    cudaGetSymbolAddress((void**)&p_c,    g_c);
    cudaGetSymbolAddress((void**)&p_temb, g_temb);

    // temb = silu(t) @ mlp_w^T + mlp_b
    temb_kernel<<<1, 512>>>(t, mlp_w, mlp_b);
    // g_buf = silu(GN1(x))
    gn_silu_kernel<<<128, 256>>>(x, gn1_s, gn1_b, p_buf);
    // g_h = conv1(g_buf) + conv1_b + temb
    conv3x3_kernel<<<dim3(16, 4, 4), 256>>>(p_buf, conv1_w, conv1_b, p_temb,
                                            nullptr, p_h);
    // g_c = 1x1 conv of cond
    cond1x1_kernel<<<dim3(32, 4, 4), 256>>>(cond, cond_w, cond_b);
    // attention (in-place on g_h) + contrast embed
    cudaFuncSetAttribute(attn_kernel,
                         cudaFuncAttributeMaxDynamicSharedMemorySize, 81920);
    attn_kernel<<<dim3(64, 4), 256, 81920>>>(p_h, p_c, ce, aim);
    // g_buf = silu(GN2(g_h))
    gn_silu_kernel<<<128, 256>>>(p_h, gn2_s, gn2_b, p_buf);
    // out = conv2(g_buf) + conv2_b + x
    conv3x3_kernel<<<dim3(16, 4, 4), 256>>>(p_buf, conv2_w, conv2_b, nullptr,
                                            x, out);
}

// round 12
// speedup vs baseline: 1.7159x; 1.1718x over previous
#include <cuda_runtime.h>

// Shapes (fixed by the problem)
#define BB   4
#define CC   128
#define HH   64
#define WW   64
#define HWSZ 4096              // 64*64
#define CHW  (CC*HWSZ)         // 128*4096

// Scratch (device globals -- no allocation allowed)
__device__ float g_buf[BB*CHW];   // silu(GN(x)) / silu(GN(h))
__device__ float g_h[BB*CHW];     // h
__device__ float g_c[BB*CHW];     // c = 1x1 conv of cond
__device__ float g_temb[BB*CC];   // time embedding

__device__ __forceinline__ float silu_f(float v) { return v / (1.0f + __expf(-v)); }

// ---- packed fp32x2 helpers (sm_103a FFMA2 path) ----
__device__ __forceinline__ unsigned long long pack2(float lo, float hi) {
    unsigned long long r;
    asm("mov.b64 %0,{%1,%2};" : "=l"(r) : "f"(lo), "f"(hi));
    return r;
}
__device__ __forceinline__ float2 unpack2(unsigned long long v) {
    float2 f;
    asm("mov.b64 {%0,%1},%2;" : "=f"(f.x), "=f"(f.y) : "l"(v));
    return f;
}
__device__ __forceinline__ void fma2(unsigned long long& d,
                                     unsigned long long a,
                                     unsigned long long b) {
    asm("fma.rn.f32x2 %0,%1,%2,%0;" : "+l"(d) : "l"(a), "l"(b));
}

// ---------------------------------------------------------------------------
// temb[b,o] = sum_k silu(t[b,k]) * mlp_w[o,k] + mlp_b[o]     (tiny)
// ---------------------------------------------------------------------------
__global__ void temb_kernel(const float* __restrict__ t,
                            const float* __restrict__ w,
                            const float* __restrict__ bias) {
    __shared__ float st[BB*512];
    int tid = threadIdx.x;
    for (int e = tid; e < BB*512; e += 512) st[e] = silu_f(t[e]);
    __syncthreads();
    int b = tid >> 7, o = tid & 127;
    const float* wr = w + o*512;
    const float* tr = st + b*512;
    float s = 0.f;
#pragma unroll 8
    for (int k = 0; k < 512; ++k) s += tr[k]*wr[k];
    g_temb[tid] = s + bias[o];
}

// ---------------------------------------------------------------------------
// GroupNorm(32 groups) + SiLU.  One block per (b,g). grid 128, block 256.
// ---------------------------------------------------------------------------
__global__ void gn_silu_kernel(const float* __restrict__ in,
                               const float* __restrict__ scale,
                               const float* __restrict__ bias,
                               float* __restrict__ out) {
    __shared__ float red[32];
    int tid = threadIdx.x;
    const float4* p = (const float4*)(in  + (size_t)blockIdx.x * 16384);
    float4*       q = (float4*)      (out + (size_t)blockIdx.x * 16384);
    float s = 0.f, sq = 0.f;
#pragma unroll 4
    for (int k = 0; k < 16; ++k) {
        float4 a = p[tid + k*256];
        s  += a.x + a.y + a.z + a.w;
        sq += a.x*a.x + a.y*a.y + a.z*a.z + a.w*a.w;
    }
#pragma unroll
    for (int o = 16; o > 0; o >>= 1) {
        s  += __shfl_xor_sync(0xffffffffu, s,  o);
        sq += __shfl_xor_sync(0xffffffffu, sq, o);
    }
    int wp = tid >> 5, lane = tid & 31;
    if (lane == 0) { red[wp] = s; red[wp + 8] = sq; }
    __syncthreads();
    if (tid == 0) {
        float ts = 0.f, tq2 = 0.f;
        for (int i = 0; i < 8; ++i) { ts += red[i]; tq2 += red[i + 8]; }
        float mean = ts * (1.0f/16384.0f);
        float var  = tq2 * (1.0f/16384.0f) - mean*mean;
        red[16] = mean;
        red[17] = rsqrtf(var + 1e-5f);
    }
    __syncthreads();
    float mean = red[16], rstd = red[17];
    int g = blockIdx.x & 31;
#pragma unroll 4
    for (int k = 0; k < 16; ++k) {
        int idx = tid + k*256;
        int c = g*4 + (idx >> 10);
        float sc = scale[c] * rstd;
        float bi = bias[c] - mean * sc;
        float4 a = p[idx];
        float4 r;
        r.x = silu_f(fmaf(a.x, sc, bi));
        r.y = silu_f(fmaf(a.y, sc, bi));
        r.z = silu_f(fmaf(a.z, sc, bi));
        r.w = silu_f(fmaf(a.w, sc, bi));
        q[idx] = r;
    }
}

// ---------------------------------------------------------------------------
// 3x3 conv, pad 1.  CTA: 16x16 pixel tile x 32 out channels, b fixed.
// grid (16 tiles, 4 o-blocks, 4 batch), block 256.
// Thread: 2x2 pixels x 8 out channels, FFMA2 inner (pairs over out channels).
// ---------------------------------------------------------------------------
__global__ void __launch_bounds__(256) conv3x3_kernel(
    const float* __restrict__ in, const float* __restrict__ wgt,
    const float* __restrict__ bias, const float* __restrict__ temb,
    const float* __restrict__ resid, float* __restrict__ out) {
    __shared__ float sIn[8*18*18];            // 2592 floats
    __shared__ float sW[72*34];               // [ci*9+rs][o], stride 34 (even)
    int tid = threadIdx.x;
    int b  = blockIdx.z;
    int ob = blockIdx.y * 32;
    int tx0 = (blockIdx.x & 3) * 16;
    int ty0 = (blockIdx.x >> 2) * 16;
    int og = tid & 3;                         // out-channel group (8 each)
    int pb = tid >> 2;                        // 0..63 pixel blocks
    int lx = (pb & 7) * 2;
    int ly = (pb >> 3) * 2;
    unsigned long long acc2[4][4];
#pragma unroll
    for (int j = 0; j < 4; ++j)
#pragma unroll
        for (int i = 0; i < 4; ++i) acc2[j][i] = 0ull;

    const float* inb = in + (size_t)b * CHW;
    const float* wb  = wgt + (size_t)ob * 1152;       // 128*9

    for (int cc = 0; cc < 16; ++cc) {
        __syncthreads();
        int ci0 = cc * 8;
        for (int e = tid; e < 2592; e += 256) {
            int ci = e / 324; int rem = e - ci*324;
            int yy = rem / 18; int xx = rem - yy*18;
            int gy = ty0 - 1 + yy, gx = tx0 - 1 + xx;
            float v = 0.f;
            if ((unsigned)gy < 64u && (unsigned)gx < 64u)
                v = inb[(ci0 + ci)*HWSZ + gy*64 + gx];
            sIn[e] = v;
        }
        for (int e = tid; e < 2304; e += 256) {
            int o = e / 72; int irs = e - o*72;       // irs = ci*9 + rs
            sW[irs*34 + o] = wb[o*1152 + ci0*9 + irs];
        }
        __syncthreads();
#pragma unroll 2
        for (int ci = 0; ci < 8; ++ci) {
            const float* sbase = sIn + ci*324;
#pragma unroll
            for (int rs = 0; rs < 9; ++rs) {
                int r = rs / 3, sx = rs - (rs/3)*3;
                const float* rowp = sbase + (ly + r)*18 + lx + sx;
                float x00 = rowp[0],  x01 = rowp[1];
                float x10 = rowp[18], x11 = rowp[19];
                unsigned long long xb0 = pack2(x00, x00);
                unsigned long long xb1 = pack2(x01, x01);
                unsigned long long xb2 = pack2(x10, x10);
                unsigned long long xb3 = pack2(x11, x11);
                const unsigned long long* wq =
                    (const unsigned long long*)(sW + (ci*9 + rs)*34 + og*8);
#pragma unroll
                for (int jp = 0; jp < 4; ++jp) {
                    unsigned long long wv = wq[jp];
                    fma2(acc2[jp][0], xb0, wv);
                    fma2(acc2[jp][1], xb1, wv);
                    fma2(acc2[jp][2], xb2, wv);
                    fma2(acc2[jp][3], xb3, wv);
                }
            }
        }
    }
    int px = tx0 + lx, py = ty0 + ly;
#pragma unroll
    for (int jp = 0; jp < 4; ++jp) {
        float2 v0 = unpack2(acc2[jp][0]);
        float2 v1 = unpack2(acc2[jp][1]);
        float2 v2 = unpack2(acc2[jp][2]);
        float2 v3 = unpack2(acc2[jp][3]);
        float pe[2][4] = {{v0.x, v1.x, v2.x, v3.x}, {v0.y, v1.y, v2.y, v3.y}};
#pragma unroll
        for (int oo = 0; oo < 2; ++oo) {
            int o = ob + og*8 + 2*jp + oo;
            float add = bias[o];
            if (temb) add += temb[b*CC + o];
            int base = (b*CC + o) * HWSZ;
#pragma unroll
            for (int dy = 0; dy < 2; ++dy)
#pragma unroll
                for (int dx = 0; dx < 2; ++dx) {
                    int idx = base + (py + dy)*64 + (px + dx);
                    float v = pe[oo][dy*2 + dx] + add;
                    if (resid) v += resid[idx];
                    out[idx] = v;
                }
        }
    }
}

// ---------------------------------------------------------------------------
// 1x1 conv -> g_c.  grid (32 o-groups, 4 px-chunks, 4 batch), block 256.
// ---------------------------------------------------------------------------
__global__ void __launch_bounds__(256) cond1x1_kernel(
    const float* __restrict__ cond, const float* __restrict__ w,
    const float* __restrict__ bias) {
    __shared__ float sw[512];
    int tid = threadIdx.x;
    int o0 = blockIdx.x * 4;
    int ch = blockIdx.y;                // 1024-px chunk
    int b  = blockIdx.z;
    for (int e = tid; e < 512; e += 256)
        sw[e] = w[(o0 + (e >> 7))*128 + (e & 127)];
    __syncthreads();
    float4 acc[4];
#pragma unroll
    for (int j = 0; j < 4; ++j) acc[j] = make_float4(0.f, 0.f, 0.f, 0.f);
    const float4* cp = (const float4*)(cond + (size_t)b * CHW) + ch*256 + tid;
#pragma unroll 4
    for (int i = 0; i < 128; ++i) {
        float4 xv = cp[(size_t)i * 1024];
#pragma unroll
        for (int j = 0; j < 4; ++j) {
            float wv = sw[j*128 + i];
            acc[j].x = fmaf(wv, xv.x, acc[j].x);
            acc[j].y = fmaf(wv, xv.y, acc[j].y);
            acc[j].z = fmaf(wv, xv.z, acc[j].z);
            acc[j].w = fmaf(wv, xv.w, acc[j].w);
        }
    }
#pragma unroll
    for (int j = 0; j < 4; ++j) {
        float bj = bias[o0 + j];
        float4 v = acc[j];
        v.x += bj; v.y += bj; v.z += bj; v.w += bj;
        ((float4*)(g_c + ((size_t)b*CC + o0 + j) * HWSZ))[ch*256 + tid] = v;
    }
}

// ---------------------------------------------------------------------------
// Streaming spatial cross-attention + contrast-embed add.
// One CTA per (b,w), 64-q chunks.  FFMA2 on both gemms.
// smem: sH [128][64], sCbuf: sC [128][68] reused as sCT [64][132], sA [64][64]
// Out-gemm pairs along c via the transposed tile: zero packs on the C side.
// grid (64 w, 4 b), block 256, dynamic smem 82KB (2 CTAs/SM).
// ---------------------------------------------------------------------------
__global__ void __launch_bounds__(256) attn_kernel(
    float* __restrict__ h, const float* __restrict__ cmat,
    const float* __restrict__ ce_tab, const int* __restrict__ aim) {
    extern __shared__ float smem[];
    float* sH  = smem;               // [128][64]           8192 floats
    float* sCb = smem + 8192;        // sC[128][68] / sCT[64][132]  8704 floats
    float* sA  = smem + 8192 + 8704; // [64][64]            4096 floats
    int tid = threadIdx.x;
    int w = blockIdx.x;
    int b = blockIdx.y;
    float*       hb = h    + (size_t)b * CHW;
    const float* cb = cmat + (size_t)b * CHW;

    for (int e = tid; e < 8192; e += 256) {
        int c = e >> 6, hh = e & 63;
        sH[e] = hb[c*HWSZ + hh*64 + w];
    }

    const int th = tid & 15;          // hh base th*4
    const int tq = tid >> 4;          // q base tq*4 (A) / c base tq*8 (Out)
    const int cb8 = tq * 8;
    const int lane = tid & 31, wp = tid >> 5;
    const int ttc = tid & 127, thf = tid >> 7;   // transpose mapping
    const float SCALE = 0.08838834764831845f;    // 1/sqrt(128)

    // Out accumulators: oa2[j][p] = {Out[cb8+2j][hh0+p], Out[cb8+2j+1][hh0+p]}
    unsigned long long oa2[4][4];
#pragma unroll
    for (int j = 0; j < 4; ++j)
#pragma unroll
        for (int p = 0; p < 4; ++p) oa2[j][p] = 0ull;

    for (int qc = 0; qc < 64; ++qc) {
        __syncthreads();              // prev iter done with sCb/sA
        {   // vectorized fill of sC (stride 68 = 17 float4)
            const float4* src4 = (const float4*)(cb + qc*64);
            for (int e = tid; e < 2048; e += 256) {
                int c = e >> 4, q4 = e & 15;
                ((float4*)sCb)[c*17 + q4] = src4[(size_t)c*1024 + q4];
            }
        }
        __syncthreads();
        // --- A = Hw^T * Cchunk ---  (4 q x 4 hh per thread, hh paired)
        unsigned long long a2[4][2];
#pragma unroll
        for (int i = 0; i < 4; ++i) { a2[i][0] = 0ull; a2[i][1] = 0ull; }
#pragma unroll 4
        for (int c = 0; c < 128; ++c) {
            ulonglong2 hv = *(const ulonglong2*)(sH + c*64 + th*4);
            float4 cv = *(const float4*)(sCb + c*68 + tq*4);
            unsigned long long hp0 = hv.x, hp1 = hv.y;
            unsigned long long c0 = pack2(cv.x, cv.x);
            unsigned long long c1 = pack2(cv.y, cv.y);
            unsigned long long c2 = pack2(cv.z, cv.z);
            unsigned long long c3 = pack2(cv.w, cv.w);
            fma2(a2[0][0], c0, hp0); fma2(a2[0][1], c0, hp1);
            fma2(a2[1][0], c1, hp0); fma2(a2[1][1], c1, hp1);
            fma2(a2[2][0], c2, hp0); fma2(a2[2][1], c2, hp1);
            fma2(a2[3][0], c3, hp0); fma2(a2[3][1], c3, hp1);
        }
        // stage C tile for transpose (reads must precede the sync below)
        float4 tv[8];
#pragma unroll
        for (int k = 0; k < 8; ++k)
            tv[k] = ((const float4*)sCb)[ttc*17 + thf*8 + k];
        // store A tile
#pragma unroll
        for (int qi = 0; qi < 4; ++qi) {
            ulonglong2 v; v.x = a2[qi][0]; v.y = a2[qi][1];
            *(ulonglong2*)(sA + (tq*4 + qi)*64 + th*4) = v;
        }
        __syncthreads();              // all sC reads done; sA visible
        // write transposed tile sCT[q][c] into the same buffer (stride 132)
#pragma unroll
        for (int k = 0; k < 8; ++k) {
            int q = (thf*8 + k)*4;
            sCb[(q+0)*132 + ttc] = tv[k].x;
            sCb[(q+1)*132 + ttc] = tv[k].y;
            sCb[(q+2)*132 + ttc] = tv[k].z;
            sCb[(q+3)*132 + ttc] = tv[k].w;
        }
        // --- softmax along hh (each sA row, 64 entries); SCALE folded ---
#pragma unroll
        for (int k = 0; k < 8; ++k) {
            int r = wp*8 + k;
            float x0 = sA[r*64 + lane]*SCALE, x1 = sA[r*64 + lane + 32]*SCALE;
            float m = fmaxf(x0, x1);
#pragma unroll
            for (int o = 16; o > 0; o >>= 1)
                m = fmaxf(m, __shfl_xor_sync(0xffffffffu, m, o));
            float e0 = __expf(x0 - m), e1 = __expf(x1 - m);
            float ss = e0 + e1;
#pragma unroll
            for (int o = 16; o > 0; o >>= 1)
                ss += __shfl_xor_sync(0xffffffffu, ss, o);
            float inv = 1.0f / ss;
            sA[r*64 + lane]      = e0 * inv;
            sA[r*64 + lane + 32] = e1 * inv;
        }
        __syncthreads();              // P and sCT ready
        // --- Out += Cchunk * P^T ---  (c paired via sCT, hh per-scalar)
#pragma unroll 2
        for (int qq = 0; qq < 64; ++qq) {
            float4 pv = *(const float4*)(sA + qq*64 + th*4);
            unsigned long long pp0 = pack2(pv.x, pv.x);
            unsigned long long pp1 = pack2(pv.y, pv.y);
            unsigned long long pp2 = pack2(pv.z, pv.z);
            unsigned long long pp3 = pack2(pv.w, pv.w);
            const ulonglong2* ct = (const ulonglong2*)(sCb + qq*132 + cb8);
            ulonglong2 ca = ct[0], cbv = ct[1];
            fma2(oa2[0][0], ca.x,  pp0); fma2(oa2[0][1], ca.x,  pp1);
            fma2(oa2[0][2], ca.x,  pp2); fma2(oa2[0][3], ca.x,  pp3);
            fma2(oa2[1][0], ca.y,  pp0); fma2(oa2[1][1], ca.y,  pp1);
            fma2(oa2[1][2], ca.y,  pp2); fma2(oa2[1][3], ca.y,  pp3);
            fma2(oa2[2][0], cbv.x, pp0); fma2(oa2[2][1], cbv.x, pp1);
            fma2(oa2[2][2], cbv.x, pp2); fma2(oa2[2][3], cbv.x, pp3);
            fma2(oa2[3][0], cbv.y, pp0); fma2(oa2[3][1], cbv.y, pp1);
            fma2(oa2[3][2], cbv.y, pp2); fma2(oa2[3][3], cbv.y, pp3);
        }
    }
    // --- epilogue: h += attn + contrast_embed[aim[b]] ---
    const float* ce = ce_tab + aim[b]*CC;
#pragma unroll
    for (int j = 0; j < 4; ++j) {
        int c0 = cb8 + 2*j;
        float ce0 = ce[c0], ce1 = ce[c0 + 1];
        float* hp0 = hb + (size_t)c0*HWSZ + w;
        float* hp1 = hp0 + HWSZ;
#pragma unroll
        for (int p = 0; p < 4; ++p) {
            float2 v = unpack2(oa2[j][p]);
            int hh = th*4 + p;
            hp0[hh*64] += v.x + ce0;
            hp1[hh*64] += v.y + ce1;
        }
    }
}

// ---------------------------------------------------------------------------
extern "C" void kernel_launch(void* const* d_in, const int* in_sizes, int n_in,
                              void* d_out, int out_size) {
    (void)in_sizes; (void)n_in; (void)out_size;
    const float* x       = (const float*)d_in[0];
    const float* t       = (const float*)d_in[1];
    const int*   aim     = (const int*)  d_in[2];
    const float* cond    = (const float*)d_in[3];
    const float* gn1_s   = (const float*)d_in[4];
    const float* gn1_b   = (const float*)d_in[5];
    const float* conv1_w = (const float*)d_in[6];
    const float* conv1_b = (const float*)d_in[7];
    const float* mlp_w   = (const float*)d_in[8];
    const float* mlp_b   = (const float*)d_in[9];
    const float* cond_w  = (const float*)d_in[10];
    const float* cond_b  = (const float*)d_in[11];
    const float* gn2_s   = (const float*)d_in[12];
    const float* gn2_b   = (const float*)d_in[13];
    const float* conv2_w = (const float*)d_in[14];
    const float* conv2_b = (const float*)d_in[15];
    const float* ce      = (const float*)d_in[16];
    float* out = (float*)d_out;

    float *p_buf, *p_h, *p_c, *p_temb;
    cudaGetSymbolAddress((void**)&p_buf,  g_buf);
    cudaGetSymbolAddress((void**)&p_h,    g_h);
    cudaGetSymbolAddress((void**)&p_c,    g_c);
    cudaGetSymbolAddress((void**)&p_temb, g_temb);

    // temb = silu(t) @ mlp_w^T + mlp_b
    temb_kernel<<<1, 512>>>(t, mlp_w, mlp_b);
    // g_buf = silu(GN1(x))
    gn_silu_kernel<<<128, 256>>>(x, gn1_s, gn1_b, p_buf);
    // g_h = conv1(g_buf) + conv1_b + temb
    conv3x3_kernel<<<dim3(16, 4, 4), 256>>>(p_buf, conv1_w, conv1_b, p_temb,
                                            nullptr, p_h);
    // g_c = 1x1 conv of cond
    cond1x1_kernel<<<dim3(32, 4, 4), 256>>>(cond, cond_w, cond_b);
    // attention (in-place on g_h) + contrast embed
    cudaFuncSetAttribute(attn_kernel,
                         cudaFuncAttributeMaxDynamicSharedMemorySize, 83968);
    attn_kernel<<<dim3(64, 4), 256, 83968>>>(p_h, p_c, ce, aim);
    // g_buf = silu(GN2(g_h))
    gn_silu_kernel<<<128, 256>>>(p_h, gn2_s, gn2_b, p_buf);
    // out = conv2(g_buf) + conv2_b + x
    conv3x3_kernel<<<dim3(16, 4, 4), 256>>>(p_buf, conv2_w, conv2_b, nullptr,
                                            x, out);
}

// round 17
// speedup vs baseline: 2.9432x; 1.7152x over previous
#include <cuda_runtime.h>
#include <cuda_fp16.h>
#include <cstdint>

// Shapes (fixed by the problem)
#define BB   4
#define CC   128
#define HH   64
#define WW   64
#define HWSZ 4096              // 64*64
#define CHW  (CC*HWSZ)         // 128*4096

// Scratch (device globals -- no allocation allowed)
__device__ float g_buf[BB*CHW];   // silu(GN(x)) / silu(GN(h))
__device__ float g_h[BB*CHW];     // h
__device__ float g_c[BB*CHW];     // c = 1x1 conv of cond
__device__ float g_temb[BB*CC];   // time embedding

__device__ __forceinline__ float silu_f(float v) { return v / (1.0f + __expf(-v)); }

// ---- packed fp32x2 helpers (conv path) ----
__device__ __forceinline__ unsigned long long pack2(float lo, float hi) {
    unsigned long long r;
    asm("mov.b64 %0,{%1,%2};" : "=l"(r) : "f"(lo), "f"(hi));
    return r;
}
__device__ __forceinline__ float2 unpack2(unsigned long long v) {
    float2 f;
    asm("mov.b64 {%0,%1},%2;" : "=f"(f.x), "=f"(f.y) : "l"(v));
    return f;
}
__device__ __forceinline__ void fma2(unsigned long long& d,
                                     unsigned long long a,
                                     unsigned long long b) {
    asm("fma.rn.f32x2 %0,%1,%2,%0;" : "+l"(d) : "l"(a), "l"(b));
}

// ---- classic warp mma (HMMA) ----
__device__ __forceinline__ void mma16816(float* d, uint32_t a0, uint32_t a1,
                                         uint32_t a2, uint32_t a3,
                                         uint32_t b0, uint32_t b1) {
    asm volatile(
        "mma.sync.aligned.m16n8k16.row.col.f32.f16.f16.f32 "
        "{%0,%1,%2,%3}, {%4,%5,%6,%7}, {%8,%9}, {%0,%1,%2,%3};"
        : "+f"(d[0]), "+f"(d[1]), "+f"(d[2]), "+f"(d[3])
        : "r"(a0), "r"(a1), "r"(a2), "r"(a3), "r"(b0), "r"(b1));
}

// ---------------------------------------------------------------------------
// temb[b,o] = sum_k silu(t[b,k]) * mlp_w[o,k] + mlp_b[o]     (tiny)
// ---------------------------------------------------------------------------
__global__ void temb_kernel(const float* __restrict__ t,
                            const float* __restrict__ w,
                            const float* __restrict__ bias) {
    __shared__ float st[BB*512];
    int tid = threadIdx.x;
    for (int e = tid; e < BB*512; e += 512) st[e] = silu_f(t[e]);
    __syncthreads();
    int b = tid >> 7, o = tid & 127;
    const float* wr = w + o*512;
    const float* tr = st + b*512;
    float s = 0.f;
#pragma unroll 8
    for (int k = 0; k < 512; ++k) s += tr[k]*wr[k];
    g_temb[tid] = s + bias[o];
}

// ---------------------------------------------------------------------------
// GroupNorm(32 groups) + SiLU.  One block per (b,g). grid 128, block 256.
// ---------------------------------------------------------------------------
__global__ void gn_silu_kernel(const float* __restrict__ in,
                               const float* __restrict__ scale,
                               const float* __restrict__ bias,
                               float* __restrict__ out) {
    __shared__ float red[32];
    int tid = threadIdx.x;
    const float4* p = (const float4*)(in  + (size_t)blockIdx.x * 16384);
    float4*       q = (float4*)      (out + (size_t)blockIdx.x * 16384);
    float s = 0.f, sq = 0.f;
#pragma unroll 4
    for (int k = 0; k < 16; ++k) {
        float4 a = p[tid + k*256];
        s  += a.x + a.y + a.z + a.w;
        sq += a.x*a.x + a.y*a.y + a.z*a.z + a.w*a.w;
    }
#pragma unroll
    for (int o = 16; o > 0; o >>= 1) {
        s  += __shfl_xor_sync(0xffffffffu, s,  o);
        sq += __shfl_xor_sync(0xffffffffu, sq, o);
    }
    int wp = tid >> 5, lane = tid & 31;
    if (lane == 0) { red[wp] = s; red[wp + 8] = sq; }
    __syncthreads();
    if (tid == 0) {
        float ts = 0.f, tq2 = 0.f;
        for (int i = 0; i < 8; ++i) { ts += red[i]; tq2 += red[i + 8]; }
        float mean = ts * (1.0f/16384.0f);
        float var  = tq2 * (1.0f/16384.0f) - mean*mean;
        red[16] = mean;
        red[17] = rsqrtf(var + 1e-5f);
    }
    __syncthreads();
    float mean = red[16], rstd = red[17];
    int g = blockIdx.x & 31;
#pragma unroll 4
    for (int k = 0; k < 16; ++k) {
        int idx = tid + k*256;
        int c = g*4 + (idx >> 10);
        float sc = scale[c] * rstd;
        float bi = bias[c] - mean * sc;
        float4 a = p[idx];
        float4 r;
        r.x = silu_f(fmaf(a.x, sc, bi));
        r.y = silu_f(fmaf(a.y, sc, bi));
        r.z = silu_f(fmaf(a.z, sc, bi));
        r.w = silu_f(fmaf(a.w, sc, bi));
        q[idx] = r;
    }
}

// ---------------------------------------------------------------------------
// 3x3 conv, pad 1.  CTA: 16x16 pixel tile x 32 out channels, b fixed.
// grid (16 tiles, 4 o-blocks, 4 batch), block 256.  FFMA2 inner.
// ---------------------------------------------------------------------------
__global__ void __launch_bounds__(256) conv3x3_kernel(
    const float* __restrict__ in, const float* __restrict__ wgt,
    const float* __restrict__ bias, const float* __restrict__ temb,
    const float* __restrict__ resid, float* __restrict__ out) {
    __shared__ float sIn[8*18*18];            // 2592 floats
    __shared__ float sW[72*34];               // [ci*9+rs][o], stride 34 (even)
    int tid = threadIdx.x;
    int b  = blockIdx.z;
    int ob = blockIdx.y * 32;
    int tx0 = (blockIdx.x & 3) * 16;
    int ty0 = (blockIdx.x >> 2) * 16;
    int og = tid & 3;                         // out-channel group (8 each)
    int pb = tid >> 2;                        // 0..63 pixel blocks
    int lx = (pb & 7) * 2;
    int ly = (pb >> 3) * 2;
    unsigned long long acc2[4][4];
#pragma unroll
    for (int j = 0; j < 4; ++j)
#pragma unroll
        for (int i = 0; i < 4; ++i) acc2[j][i] = 0ull;

    const float* inb = in + (size_t)b * CHW;
    const float* wb  = wgt + (size_t)ob * 1152;       // 128*9

    for (int cc = 0; cc < 16; ++cc) {
        __syncthreads();
        int ci0 = cc * 8;
        for (int e = tid; e < 2592; e += 256) {
            int ci = e / 324; int rem = e - ci*324;
            int yy = rem / 18; int xx = rem - yy*18;
            int gy = ty0 - 1 + yy, gx = tx0 - 1 + xx;
            float v = 0.f;
            if ((unsigned)gy < 64u && (unsigned)gx < 64u)
                v = inb[(ci0 + ci)*HWSZ + gy*64 + gx];
            sIn[e] = v;
        }
        for (int e = tid; e < 2304; e += 256) {
            int o = e / 72; int irs = e - o*72;       // irs = ci*9 + rs
            sW[irs*34 + o] = wb[o*1152 + ci0*9 + irs];
        }
        __syncthreads();
#pragma unroll 2
        for (int ci = 0; ci < 8; ++ci) {
            const float* sbase = sIn + ci*324;
#pragma unroll
            for (int rs = 0; rs < 9; ++rs) {
                int r = rs / 3, sx = rs - (rs/3)*3;
                const float* rowp = sbase + (ly + r)*18 + lx + sx;
                float x00 = rowp[0],  x01 = rowp[1];
                float x10 = rowp[18], x11 = rowp[19];
                unsigned long long xb0 = pack2(x00, x00);
                unsigned long long xb1 = pack2(x01, x01);
                unsigned long long xb2 = pack2(x10, x10);
                unsigned long long xb3 = pack2(x11, x11);
                const unsigned long long* wq =
                    (const unsigned long long*)(sW + (ci*9 + rs)*34 + og*8);
#pragma unroll
                for (int jp = 0; jp < 4; ++jp) {
                    unsigned long long wv = wq[jp];
                    fma2(acc2[jp][0], xb0, wv);
                    fma2(acc2[jp][1], xb1, wv);
                    fma2(acc2[jp][2], xb2, wv);
                    fma2(acc2[jp][3], xb3, wv);
                }
            }
        }
    }
    int px = tx0 + lx, py = ty0 + ly;
#pragma unroll
    for (int jp = 0; jp < 4; ++jp) {
        float2 v0 = unpack2(acc2[jp][0]);
        float2 v1 = unpack2(acc2[jp][1]);
        float2 v2 = unpack2(acc2[jp][2]);
        float2 v3 = unpack2(acc2[jp][3]);
        float pe[2][4] = {{v0.x, v1.x, v2.x, v3.x}, {v0.y, v1.y, v2.y, v3.y}};
#pragma unroll
        for (int oo = 0; oo < 2; ++oo) {
            int o = ob + og*8 + 2*jp + oo;
            float add = bias[o];
            if (temb) add += temb[b*CC + o];
            int base = (b*CC + o) * HWSZ;
#pragma unroll
            for (int dy = 0; dy < 2; ++dy)
#pragma unroll
                for (int dx = 0; dx < 2; ++dx) {
                    int idx = base + (py + dy)*64 + (px + dx);
                    float v = pe[oo][dy*2 + dx] + add;
                    if (resid) v += resid[idx];
                    out[idx] = v;
                }
        }
    }
}

// ---------------------------------------------------------------------------
// 1x1 conv -> g_c.  grid (32 o-groups, 4 px-chunks, 4 batch), block 256.
// ---------------------------------------------------------------------------
__global__ void __launch_bounds__(256) cond1x1_kernel(
    const float* __restrict__ cond, const float* __restrict__ w,
    const float* __restrict__ bias) {
    __shared__ float sw[512];
    int tid = threadIdx.x;
    int o0 = blockIdx.x * 4;
    int ch = blockIdx.y;                // 1024-px chunk
    int b  = blockIdx.z;
    for (int e = tid; e < 512; e += 256)
        sw[e] = w[(o0 + (e >> 7))*128 + (e & 127)];
    __syncthreads();
    float4 acc[4];
#pragma unroll
    for (int j = 0; j < 4; ++j) acc[j] = make_float4(0.f, 0.f, 0.f, 0.f);
    const float4* cp = (const float4*)(cond + (size_t)b * CHW) + ch*256 + tid;
#pragma unroll 4
    for (int i = 0; i < 128; ++i) {
        float4 xv = cp[(size_t)i * 1024];
#pragma unroll
        for (int j = 0; j < 4; ++j) {
            float wv = sw[j*128 + i];
            acc[j].x = fmaf(wv, xv.x, acc[j].x);
            acc[j].y = fmaf(wv, xv.y, acc[j].y);
            acc[j].z = fmaf(wv, xv.z, acc[j].z);
            acc[j].w = fmaf(wv, xv.w, acc[j].w);
        }
    }
#pragma unroll
    for (int j = 0; j < 4; ++j) {
        float bj = bias[o0 + j];
        float4 v = acc[j];
        v.x += bj; v.y += bj; v.z += bj; v.w += bj;
        ((float4*)(g_c + ((size_t)b*CC + o0 + j) * HWSZ))[ch*256 + tid] = v;
    }
}

// ---------------------------------------------------------------------------
// Attention via classic warp mma (fp16 in / fp32 accum).
// One CTA per (b,w).  Per 64-q chunk:
//   A-gemm: D1[q][hh] = sum_c C^T[q][c]*H[c][hh]  (A=sCt[q][c], B=sHt[hh][c])
//   softmax over hh in registers (cross-warp stats via smem)
//   P fp16 -> sPt[hh][q]
//   Out-gemm: D[c][hh] += sum_q C[c][q]*P[q][hh]  (A=sC[c][q], B=sPt[hh][q])
//   accumulated in registers across all chunks.
// Warp tiling: A-gemm warp = (q-tile 16)=(wid&3), (hh-half 32)=(wid>>2);
//              Out-gemm warp = c-tile 16 = wid, full hh 64.
// smem (halfs): sHt[64][136] | sCt[64][136] | sC[128][72] | sPt[64][72]
//   + f32 sMax[2][64], sSum[2][64].   Total 63488 B -> 3 CTAs/SM.
// grid (64 w, 4 b), block 256.
// ---------------------------------------------------------------------------
__global__ void __launch_bounds__(256, 3) attn_kernel(
    float* __restrict__ h, const float* __restrict__ cmat,
    const float* __restrict__ ce_tab, const int* __restrict__ aim) {
    extern __shared__ __half smem_h[];
    __half* sHt = smem_h;             // [64][136]
    __half* sCt = smem_h + 8704;      // [64][136]
    __half* sC  = smem_h + 17408;     // [128][72]
    __half* sPt = smem_h + 26624;     // [64][72]
    float* sMax = (float*)(smem_h + 31232);   // [2][64]
    float* sSum = sMax + 128;                 // [2][64]

    int tid  = threadIdx.x;
    int lane = tid & 31;
    int wid  = tid >> 5;
    int g    = lane >> 2;           // 0..7  (row within 8)
    int qd   = (lane & 3) * 2;      // col pair base within tile
    int w = blockIdx.x;
    int b = blockIdx.y;
    float*       hb = h    + (size_t)b * CHW;
    const float* cb = cmat + (size_t)b * CHW;

    // fill sHt[hh][c] = fp16(h[c][hh*64+w])   (once)
    for (int e = tid; e < 8192; e += 256) {
        int c = e >> 6, hh = e & 63;
        sHt[hh*136 + c] = __float2half(hb[c*HWSZ + hh*64 + w]);
    }

    const int qt = (wid & 3) * 16;    // A-gemm q tile
    const int nh = wid >> 2;          // hh half (0/1)
    const int ct = wid * 16;          // Out-gemm c tile
    const float SCALE = 0.08838834764831845f;

    float od[8][4];                   // Out accum: 8 hh-tiles x 4
#pragma unroll
    for (int nt = 0; nt < 8; ++nt)
#pragma unroll
        for (int i = 0; i < 4; ++i) od[nt][i] = 0.f;

    for (int qc = 0; qc < 64; ++qc) {
        __syncthreads();              // prev chunk's gemms done with tiles
        {   // fill sC[c][q] and sCt[q][c] in fp16
            const float4* src4 = (const float4*)(cb + qc*64);
            for (int e = tid; e < 2048; e += 256) {
                int c = e >> 4, q4 = e & 15;
                float4 v = src4[(size_t)c*1024 + q4];
                __half h0 = __float2half(v.x), h1 = __float2half(v.y);
                __half h2 = __float2half(v.z), h3 = __float2half(v.w);
                __half* cr = sC + c*72 + q4*4;
                *(__half2*)(cr)     = __halves2half2(h0, h1);
                *(__half2*)(cr + 2) = __halves2half2(h2, h3);
                int q0 = q4*4;
                sCt[(q0+0)*136 + c] = h0;
                sCt[(q0+1)*136 + c] = h1;
                sCt[(q0+2)*136 + c] = h2;
                sCt[(q0+3)*136 + c] = h3;
            }
        }
        __syncthreads();
        // --- A-gemm: scores ad[nt][4] for (q-tile qt, hh-half nh) ---
        float ad[4][4];
#pragma unroll
        for (int nt = 0; nt < 4; ++nt)
#pragma unroll
            for (int i = 0; i < 4; ++i) ad[nt][i] = 0.f;
        const __half* arow0 = sCt + (qt + g)*136;
        const __half* arow1 = sCt + (qt + g + 8)*136;
#pragma unroll
        for (int ks = 0; ks < 8; ++ks) {
            int cc = ks*16 + qd;
            uint32_t a0 = *(const uint32_t*)(arow0 + cc);
            uint32_t a1 = *(const uint32_t*)(arow1 + cc);
            uint32_t a2 = *(const uint32_t*)(arow0 + cc + 8);
            uint32_t a3 = *(const uint32_t*)(arow1 + cc + 8);
#pragma unroll
            for (int nt = 0; nt < 4; ++nt) {
                const __half* brow = sHt + (nh*32 + nt*8 + g)*136 + cc;
                uint32_t b0 = *(const uint32_t*)(brow);
                uint32_t b1 = *(const uint32_t*)(brow + 8);
                mma16816(ad[nt], a0, a1, a2, a3, b0, b1);
            }
        }
        // --- softmax over hh (rows = q) ---
        float m0 = -1e30f, m1 = -1e30f;
#pragma unroll
        for (int nt = 0; nt < 4; ++nt) {
            m0 = fmaxf(m0, fmaxf(ad[nt][0], ad[nt][1]));
            m1 = fmaxf(m1, fmaxf(ad[nt][2], ad[nt][3]));
        }
        m0 = fmaxf(m0, __shfl_xor_sync(0xffffffffu, m0, 1));
        m0 = fmaxf(m0, __shfl_xor_sync(0xffffffffu, m0, 2));
        m1 = fmaxf(m1, __shfl_xor_sync(0xffffffffu, m1, 1));
        m1 = fmaxf(m1, __shfl_xor_sync(0xffffffffu, m1, 2));
        if ((lane & 3) == 0) {
            sMax[nh*64 + qt + g]     = m0;
            sMax[nh*64 + qt + g + 8] = m1;
        }
        __syncthreads();
        float M0 = fmaxf(m0, sMax[(nh^1)*64 + qt + g]);
        float M1 = fmaxf(m1, sMax[(nh^1)*64 + qt + g + 8]);
        float s0 = 0.f, s1 = 0.f;
#pragma unroll
        for (int nt = 0; nt < 4; ++nt) {
            ad[nt][0] = __expf((ad[nt][0] - M0) * SCALE);
            ad[nt][1] = __expf((ad[nt][1] - M0) * SCALE);
            ad[nt][2] = __expf((ad[nt][2] - M1) * SCALE);
            ad[nt][3] = __expf((ad[nt][3] - M1) * SCALE);
            s0 += ad[nt][0] + ad[nt][1];
            s1 += ad[nt][2] + ad[nt][3];
        }
        s0 += __shfl_xor_sync(0xffffffffu, s0, 1);
        s0 += __shfl_xor_sync(0xffffffffu, s0, 2);
        s1 += __shfl_xor_sync(0xffffffffu, s1, 1);
        s1 += __shfl_xor_sync(0xffffffffu, s1, 2);
        if ((lane & 3) == 0) {
            sSum[nh*64 + qt + g]     = s0;
            sSum[nh*64 + qt + g + 8] = s1;
        }
        __syncthreads();
        float i0 = 1.0f / (s0 + sSum[(nh^1)*64 + qt + g]);
        float i1 = 1.0f / (s1 + sSum[(nh^1)*64 + qt + g + 8]);
        // store P^T[hh][q] fp16
#pragma unroll
        for (int nt = 0; nt < 4; ++nt) {
            int hh0 = nh*32 + nt*8 + qd;
            sPt[(hh0+0)*72 + qt + g]     = __float2half(ad[nt][0] * i0);
            sPt[(hh0+1)*72 + qt + g]     = __float2half(ad[nt][1] * i0);
            sPt[(hh0+0)*72 + qt + g + 8] = __float2half(ad[nt][2] * i1);
            sPt[(hh0+1)*72 + qt + g + 8] = __float2half(ad[nt][3] * i1);
        }
        __syncthreads();              // sPt ready
        // --- Out-gemm: od += C[c][q] * P[q][hh] ---
        const __half* orow0 = sC + (ct + g)*72;
        const __half* orow1 = sC + (ct + g + 8)*72;
#pragma unroll
        for (int ks = 0; ks < 4; ++ks) {
            int qq = ks*16 + qd;
            uint32_t a0 = *(const uint32_t*)(orow0 + qq);
            uint32_t a1 = *(const uint32_t*)(orow1 + qq);
            uint32_t a2 = *(const uint32_t*)(orow0 + qq + 8);
            uint32_t a3 = *(const uint32_t*)(orow1 + qq + 8);
#pragma unroll
            for (int nt = 0; nt < 8; ++nt) {
                const __half* brow = sPt + (nt*8 + g)*72 + qq;
                uint32_t b0 = *(const uint32_t*)(brow);
                uint32_t b1 = *(const uint32_t*)(brow + 8);
                mma16816(od[nt], a0, a1, a2, a3, b0, b1);
            }
        }
    }
    // --- epilogue: h += attn + contrast_embed[aim[b]] ---
    const float* ce = ce_tab + aim[b]*CC;
    int c0 = ct + g, c1 = ct + g + 8;
    float ceA = ce[c0], ceB = ce[c1];
    float* hp0 = hb + (size_t)c0*HWSZ + w;
    float* hp1 = hb + (size_t)c1*HWSZ + w;
#pragma unroll
    for (int nt = 0; nt < 8; ++nt) {
        int hh = nt*8 + qd;
        hp0[hh*64]       += od[nt][0] + ceA;
        hp0[(hh+1)*64]   += od[nt][1] + ceA;
        hp1[hh*64]       += od[nt][2] + ceB;
        hp1[(hh+1)*64]   += od[nt][3] + ceB;
    }
}

// ---------------------------------------------------------------------------
extern "C" void kernel_launch(void* const* d_in, const int* in_sizes, int n_in,
                              void* d_out, int out_size) {
    (void)in_sizes; (void)n_in; (void)out_size;
    const float* x       = (const float*)d_in[0];
    const float* t       = (const float*)d_in[1];
    const int*   aim     = (const int*)  d_in[2];
    const float* cond    = (const float*)d_in[3];
    const float* gn1_s   = (const float*)d_in[4];
    const float* gn1_b   = (const float*)d_in[5];
    const float* conv1_w = (const float*)d_in[6];
    const float* conv1_b = (const float*)d_in[7];
    const float* mlp_w   = (const float*)d_in[8];
    const float* mlp_b   = (const float*)d_in[9];
    const float* cond_w  = (const float*)d_in[10];
    const float* cond_b  = (const float*)d_in[11];
    const float* gn2_s   = (const float*)d_in[12];
    const float* gn2_b   = (const float*)d_in[13];
    const float* conv2_w = (const float*)d_in[14];
    const float* conv2_b = (const float*)d_in[15];
    const float* ce      = (const float*)d_in[16];
    float* out = (float*)d_out;

    float *p_buf, *p_h, *p_c, *p_temb;
    cudaGetSymbolAddress((void**)&p_buf,  g_buf);
    cudaGetSymbolAddress((void**)&p_h,    g_h);
    cudaGetSymbolAddress((void**)&p_c,    g_c);
    cudaGetSymbolAddress((void**)&p_temb, g_temb);

    // temb = silu(t) @ mlp_w^T + mlp_b
    temb_kernel<<<1, 512>>>(t, mlp_w, mlp_b);
    // g_buf = silu(GN1(x))
    gn_silu_kernel<<<128, 256>>>(x, gn1_s, gn1_b, p_buf);
    // g_h = conv1(g_buf) + conv1_b + temb
    conv3x3_kernel<<<dim3(16, 4, 4), 256>>>(p_buf, conv1_w, conv1_b, p_temb,
                                            nullptr, p_h);
    // g_c = 1x1 conv of cond
    cond1x1_kernel<<<dim3(32, 4, 4), 256>>>(cond, cond_w, cond_b);
    // attention (in-place on g_h) + contrast embed
    cudaFuncSetAttribute(attn_kernel,
                         cudaFuncAttributeMaxDynamicSharedMemorySize, 63488);
    attn_kernel<<<dim3(64, 4), 256, 63488>>>(p_h, p_c, ce, aim);
    // g_buf = silu(GN2(g_h))
    gn_silu_kernel<<<128, 256>>>(p_h, gn2_s, gn2_b, p_buf);
    // out = conv2(g_buf) + conv2_b + x
    conv3x3_kernel<<<dim3(16, 4, 4), 256>>>(p_buf, conv2_w, conv2_b, nullptr,
                                            x, out);
}